// round 1
// baseline (speedup 1.0000x reference)
#include <cuda_runtime.h>

// ---------------------------------------------------------------------------
// DLinear_436: collapsed unfold->einsum->fold to a per-pixel linear map with
// position-class weights.  B=32, T=12, H=W=64, C=4, O=48, K=8, S=4, DEC_K=25.
//
// Position classes (per axis, 12 each):
//   h<4      : hc=h,       I={h}
//   4<=h<60  : hc=4+h%4,   I={h%4, h%4+4}
//   h>=60    : hc=8+h%4,   I={h%4+4}
//
// Moving-average trend (window 25, edge pad 12, T=12) is affine in t:
//   trend[t,c] = (S_c + 12*x0_c + x11_c + t*(x11_c - x0_c)) / 25
// so trend contribution = alpha_c*D0[o,c] + beta_c*D1[o,c] with
//   D0 = sum_t (Wt_eff - Ws_eff),  D1 = sum_t t*(Wt_eff - Ws_eff).
// ---------------------------------------------------------------------------

#define NB    32
#define T_IN  12
#define HH    64
#define WW    64
#define C_IN  4
#define NO    48
#define TC    48     // T_IN * C_IN
#define NCLS  144    // 12 hc * 12 wc
#define HW    4096   // H*W

// Per-class folded weight tables (prep kernel output)
__device__ float gW [NCLS][NO][TC];   // Ws_eff, layout [cls][o][tc]
__device__ float gD0[NCLS][NO][4];
__device__ float gD1[NCLS][NO][4];
__device__ float gB [NCLS][NO];

__device__ __forceinline__ int class_ilist(int hc, int idx[2]) {
    if (hc < 4)  { idx[0] = hc;                      return 1; }
    if (hc < 8)  { idx[0] = hc - 4; idx[1] = hc;     return 2; }
    idx[0] = hc - 4;                                 return 1;
}

// ---------------------------------------------------------------------------
// Prep: fold raw weights into per-class tables.  144 blocks, trivial cost.
// ---------------------------------------------------------------------------
__global__ void dlinear_prep_kernel(const float* __restrict__ w_s,
                                    const float* __restrict__ b_s,
                                    const float* __restrict__ w_t,
                                    const float* __restrict__ b_t) {
    int cls = blockIdx.x;
    int hc = cls / 12, wc = cls % 12;
    int il[2], jl[2];
    int ni = class_ilist(hc, il);
    int nj = class_ilist(wc, jl);

    // Ws_eff[o][tc] = sum_{i in I, j in J} w_s[o, t, c, i, j]   (tc = t*4+c)
    for (int idx = threadIdx.x; idx < NO * TC; idx += blockDim.x) {
        int o = idx / TC, tc = idx % TC;
        const float* wp = w_s + (o * TC + tc) * 64;   // (o*48+tc)*64 + i*8 + j
        float s = 0.f;
        for (int a = 0; a < ni; a++)
            for (int e = 0; e < nj; e++)
                s += wp[il[a] * 8 + jl[e]];
        gW[cls][o][tc] = s;
    }

    // D0/D1 over t of (w_t - w_s) folded
    for (int idx = threadIdx.x; idx < NO * 4; idx += blockDim.x) {
        int o = idx / 4, c = idx % 4;
        float d0 = 0.f, d1 = 0.f;
        for (int t = 0; t < T_IN; t++) {
            const float* ps = w_s + ((o * T_IN + t) * 4 + c) * 64;
            const float* pt = w_t + ((o * T_IN + t) * 4 + c) * 64;
            float d = 0.f;
            for (int a = 0; a < ni; a++)
                for (int e = 0; e < nj; e++) {
                    int off = il[a] * 8 + jl[e];
                    d += pt[off] - ps[off];
                }
            d0 += d;
            d1 += (float)t * d;
        }
        gD0[cls][o][c] = d0;
        gD1[cls][o][c] = d1;
    }

    // folded bias (b_s + b_t)
    for (int o = threadIdx.x; o < NO; o += blockDim.x) {
        float s = 0.f;
        for (int a = 0; a < ni; a++)
            for (int e = 0; e < nj; e++) {
                int off = o * 64 + il[a] * 8 + jl[e];
                s += b_s[off] + b_t[off];
            }
        gB[cls][o] = s;
    }
}

// ---------------------------------------------------------------------------
// Main: block = (class, 256-pixel chunk).  Weights uniform across the block,
// staged in ~11KB smem and read via LDS.128 (1 LDS per 4 FMA).
// ---------------------------------------------------------------------------
__global__ __launch_bounds__(256)
void dlinear_main_kernel(const float* __restrict__ x, float* __restrict__ out) {
    int cls = blockIdx.x;
    int hc = cls / 12, wc = cls % 12;
    int nrows = (hc >= 4 && hc < 8) ? 14 : 1;
    int ncols = (wc >= 4 && wc < 8) ? 14 : 1;
    int h0 = (hc < 8) ? hc : hc + 52;   // hc<4: h=hc; interior: h=hc+4r; high: h=hc+52
    int w0 = (wc < 8) ? wc : wc + 52;
    int per_img = nrows * ncols;
    int npx = per_img * NB;

    if ((int)(blockIdx.y * blockDim.x) >= npx) return;   // whole block empty

    __shared__ __align__(16) float sW [NO][TC];
    __shared__ __align__(16) float sD0[NO][4];
    __shared__ __align__(16) float sD1[NO][4];
    __shared__ float sB[NO];

    for (int i = threadIdx.x; i < NO * TC; i += blockDim.x)
        (&sW[0][0])[i] = (&gW[cls][0][0])[i];
    for (int i = threadIdx.x; i < NO * 4; i += blockDim.x) {
        (&sD0[0][0])[i] = (&gD0[cls][0][0])[i];
        (&sD1[0][0])[i] = (&gD1[cls][0][0])[i];
    }
    for (int i = threadIdx.x; i < NO; i += blockDim.x)
        sB[i] = gB[cls][i];
    __syncthreads();

    int p = blockIdx.y * blockDim.x + threadIdx.x;
    if (p >= npx) return;

    int b   = p / per_img;
    int rem = p - b * per_img;
    int r   = rem / ncols;
    int s   = rem - r * ncols;
    int h = h0 + 4 * r;
    int w = w0 + 4 * s;

    // Load this pixel's x[t, c] (C=4 contiguous -> float4 per t)
    float xr[TC];
    const float4* xp = (const float4*)x + (b * T_IN * HW + h * WW + w);
    #pragma unroll
    for (int t = 0; t < T_IN; t++) {
        float4 v = xp[t * HW];
        xr[t * 4 + 0] = v.x; xr[t * 4 + 1] = v.y;
        xr[t * 4 + 2] = v.z; xr[t * 4 + 3] = v.w;
    }

    // Trend coefficients per c
    float alpha[4], beta[4];
    #pragma unroll
    for (int c = 0; c < 4; c++) {
        float S = 0.f;
        #pragma unroll
        for (int t = 0; t < T_IN; t++) S += xr[t * 4 + c];
        alpha[c] = (S + 12.f * xr[c] + xr[44 + c]) * (1.f / 25.f);
        beta[c]  = (xr[44 + c] - xr[c]) * (1.f / 25.f);
    }

    float4* op = (float4*)out + (b * T_IN * HW + h * WW + w);
    #pragma unroll
    for (int to = 0; to < 12; to++) {
        float accv[4];
        #pragma unroll
        for (int co = 0; co < 4; co++) {
            int o = to * 4 + co;
            float a = sB[o];
            const float4* wrow = (const float4*)sW[o];
            #pragma unroll
            for (int q = 0; q < 12; q++) {
                float4 wv = wrow[q];
                a += xr[q * 4 + 0] * wv.x;
                a += xr[q * 4 + 1] * wv.y;
                a += xr[q * 4 + 2] * wv.z;
                a += xr[q * 4 + 3] * wv.w;
            }
            float4 d0 = *(const float4*)sD0[o];
            float4 d1 = *(const float4*)sD1[o];
            a += alpha[0] * d0.x + alpha[1] * d0.y + alpha[2] * d0.z + alpha[3] * d0.w;
            a += beta[0]  * d1.x + beta[1]  * d1.y + beta[2]  * d1.z + beta[3]  * d1.w;
            accv[co] = a;
        }
        float4 acc = make_float4(accv[0], accv[1], accv[2], accv[3]);
        op[to * HW] = acc;
    }
}

// ---------------------------------------------------------------------------
extern "C" void kernel_launch(void* const* d_in, const int* in_sizes, int n_in,
                              void* d_out, int out_size) {
    const float* x   = (const float*)d_in[0];
    const float* w_s = (const float*)d_in[1];
    const float* b_s = (const float*)d_in[2];
    const float* w_t = (const float*)d_in[3];
    const float* b_t = (const float*)d_in[4];
    float* out = (float*)d_out;

    dlinear_prep_kernel<<<NCLS, 256>>>(w_s, b_s, w_t, b_t);

    // Max pixels per class = 14*14*32 = 6272 -> 25 chunks of 256
    dim3 grid(NCLS, 25);
    dlinear_main_kernel<<<grid, 256>>>(x, out);
}